// round 14
// baseline (speedup 1.0000x reference)
#include <cuda_runtime.h>
#include <cuda_bf16.h>
#include <cuda_fp16.h>
#include <math_constants.h>

// ---------------------------------------------------------------------------
// GAT_50861002719235: 3-layer GAT, N=50000, E=1.6M, H=4, D=32/32/47
// R13 base (489us) + multi-block CSR scan (scan_k 71us -> ~14us).
// ---------------------------------------------------------------------------

#define NN 50000
#define EE 1600000
#define HH 4
#define FIN 100
#define HD 128
#define CC 47
#define DP 48
#define HCP 192
#define NEG_SLOPE 0.2f

#define SCAN_B 2048
#define SCAN_NB ((NN + SCAN_B - 1) / SCAN_B)   // 25

__device__ int      g_row_ptr[NN + 1];
__device__ int      g_cursor[NN];
__device__ int      g_col_src[EE];
__device__ int      g_bsum[SCAN_NB];
__device__ int      g_boff[SCAN_NB];
__device__ float    g_fs[NN * HCP];
__device__ float    g_h [NN * HCP];
__device__ float    g_el[NN * HH];
__device__ float    g_er[NN * HH];
__device__ unsigned g_maxel_enc[12];

__device__ __forceinline__ float lrelu(float x) { return (x >= 0.f) ? x : NEG_SLOPE * x; }
__device__ __forceinline__ float4 lrelu4(float4 v) {
    return make_float4(lrelu(v.x), lrelu(v.y), lrelu(v.z), lrelu(v.w));
}
__device__ __forceinline__ unsigned enc_f(float f) {
    unsigned b = __float_as_uint(f);
    return (b & 0x80000000u) ? ~b : (b | 0x80000000u);
}
__device__ __forceinline__ float dec_f(unsigned u) {
    unsigned b = (u & 0x80000000u) ? (u ^ 0x80000000u) : ~u;
    return __uint_as_float(b);
}

__global__ void init_k() {
    if (threadIdx.x < 12) g_maxel_enc[threadIdx.x] = 0u;
}

// ---------------------------------------------------------------------------
// CSR build (multi-block scan)
// ---------------------------------------------------------------------------
__global__ void zero_counts_k() {
    int i = blockIdx.x * blockDim.x + threadIdx.x;
    if (i < NN) g_cursor[i] = 0;
}
__global__ void count_k(const int* __restrict__ dst) {
    int e = blockIdx.x * blockDim.x + threadIdx.x;
    if (e < EE) atomicAdd(&g_cursor[dst[e]], 1);
}
// A: per-block sum of 2048 counts
__global__ void scanA_k() {
    __shared__ int sh[1024];
    int b = blockIdx.x, t = threadIdx.x;
    int i0 = b * SCAN_B + t * 2;
    int c0 = (i0     < NN) ? g_cursor[i0]     : 0;
    int c1 = (i0 + 1 < NN) ? g_cursor[i0 + 1] : 0;
    sh[t] = c0 + c1;
    __syncthreads();
    for (int o = 512; o >= 1; o >>= 1) {
        if (t < o) sh[t] += sh[t + o];
        __syncthreads();
    }
    if (t == 0) g_bsum[b] = sh[0];
}
// B: exclusive scan of 25 block sums (1 warp)
__global__ void scanB_k() {
    int t = threadIdx.x;
    int s = (t < SCAN_NB) ? g_bsum[t] : 0;
    int v = s;
    for (int o = 1; o < 32; o <<= 1) {
        int u = __shfl_up_sync(0xffffffffu, v, o);
        if (t >= o) v += u;
    }
    if (t < SCAN_NB) g_boff[t] = v - s;
    if (t == 31) g_row_ptr[NN] = v;
}
// C: local scan + global offset -> row_ptr, cursor
__global__ void scanC_k() {
    __shared__ int sh[1024];
    int b = blockIdx.x, t = threadIdx.x;
    int i0 = b * SCAN_B + t * 2;
    int c0 = (i0     < NN) ? g_cursor[i0]     : 0;
    int c1 = (i0 + 1 < NN) ? g_cursor[i0 + 1] : 0;
    int pair = c0 + c1;
    sh[t] = pair;
    __syncthreads();
    for (int o = 1; o < 1024; o <<= 1) {
        int u = (t >= o) ? sh[t - o] : 0;
        __syncthreads();
        sh[t] += u;
        __syncthreads();
    }
    int base = g_boff[b] + sh[t] - pair;
    if (i0 < NN)     { g_row_ptr[i0]     = base;      g_cursor[i0]     = base; }
    if (i0 + 1 < NN) { g_row_ptr[i0 + 1] = base + c0; g_cursor[i0 + 1] = base + c0; }
}
__global__ void fill_k(const int* __restrict__ src, const int* __restrict__ dst) {
    int e = blockIdx.x * blockDim.x + threadIdx.x;
    if (e < EE) { int p = atomicAdd(&g_cursor[dst[e]], 1); g_col_src[p] = src[e]; }
}

// ---------------------------------------------------------------------------
// Tensor-core GEMM with optional fused el/er epilogue (layers 0/1).
// ---------------------------------------------------------------------------
__device__ __forceinline__ void mma16816(float* c, const unsigned* a,
                                         unsigned b0, unsigned b1) {
    asm volatile(
        "mma.sync.aligned.m16n8k16.row.col.f32.f16.f16.f32 "
        "{%0,%1,%2,%3}, {%4,%5,%6,%7}, {%8,%9}, {%0,%1,%2,%3};"
        : "+f"(c[0]), "+f"(c[1]), "+f"(c[2]), "+f"(c[3])
        : "r"(a[0]), "r"(a[1]), "r"(a[2]), "r"(a[3]), "r"(b0), "r"(b1));
}

template<int K, int KP, int AST, int BR, int BCP, int COLS, int NWR, int TPB,
         int OST, bool PADMAP, bool ELR>
__global__ void gemm_mma_k(const float* __restrict__ A, const float* __restrict__ W,
                           float* __restrict__ out, unsigned* __restrict__ mslot,
                           const float* __restrict__ al, const float* __restrict__ ar) {
    extern __shared__ __half smem[];
    const int STR = KP + 8;
    __half* A_s = smem;
    __half* W_s = smem + BR * STR;
    int n0 = blockIdx.x * BR;
    int tid = threadIdx.x;

    for (int idx = tid; idx < BR * (KP / 2); idx += TPB) {
        int r = idx / (KP / 2);
        int k = (idx % (KP / 2)) * 2;
        int n = n0 + r;
        __half2 hv;
        if (n < NN && k + 1 < K) {
            float2 f = *(const float2*)(A + (long)n * AST + k);
            hv = __float22half2_rn(f);
        } else {
            hv = __half2half2(__float2half_rn(0.f));
        }
        *(__half2*)&A_s[r * STR + k] = hv;
    }
    for (int idx = tid; idx < BCP * KP; idx += TPB) {
        int k = idx / BCP;
        int c = idx % BCP;
        float v = (c < COLS && k < K) ? W[(long)k * COLS + c] : 0.f;
        W_s[c * STR + k] = __float2half_rn(v);
    }
    __syncthreads();

    int wid = tid >> 5, lane = tid & 31;
    int g = lane >> 2, q = lane & 3;
    int mrow = (wid % NWR) * 32;
    int ncol = (wid / NWR) * 32;

    float acc[2][4][4];
#pragma unroll
    for (int mi = 0; mi < 2; mi++)
#pragma unroll
        for (int ni = 0; ni < 4; ni++)
#pragma unroll
            for (int p = 0; p < 4; p++) acc[mi][ni][p] = 0.f;

#pragma unroll
    for (int ks = 0; ks < KP / 16; ks++) {
        int k0 = ks * 16;
        unsigned a[2][4];
#pragma unroll
        for (int mi = 0; mi < 2; mi++) {
            int rb = mrow + mi * 16;
            a[mi][0] = *(const unsigned*)&A_s[(rb + g) * STR + k0 + 2 * q];
            a[mi][1] = *(const unsigned*)&A_s[(rb + g + 8) * STR + k0 + 2 * q];
            a[mi][2] = *(const unsigned*)&A_s[(rb + g) * STR + k0 + 2 * q + 8];
            a[mi][3] = *(const unsigned*)&A_s[(rb + g + 8) * STR + k0 + 2 * q + 8];
        }
#pragma unroll
        for (int ni = 0; ni < 4; ni++) {
            int cb = ncol + ni * 8 + g;
            unsigned b0 = *(const unsigned*)&W_s[cb * STR + k0 + 2 * q];
            unsigned b1 = *(const unsigned*)&W_s[cb * STR + k0 + 2 * q + 8];
            mma16816(acc[0][ni], a[0], b0, b1);
            mma16816(acc[1][ni], a[1], b0, b1);
        }
    }

#pragma unroll
    for (int mi = 0; mi < 2; mi++) {
#pragma unroll
        for (int ni = 0; ni < 4; ni++) {
            int c0 = ncol + ni * 8 + 2 * q;
            int r0 = n0 + mrow + mi * 16 + g;
            int r1 = r0 + 8;
            if (!PADMAP) {
                if (r0 < NN) *(float2*)&out[(long)r0 * OST + c0] =
                    make_float2(acc[mi][ni][0], acc[mi][ni][1]);
                if (r1 < NN) *(float2*)&out[(long)r1 * OST + c0] =
                    make_float2(acc[mi][ni][2], acc[mi][ni][3]);
            } else {
                int c1 = c0 + 1;
                int cp0 = (c0 / CC) * DP + (c0 % CC);
                int cp1 = (c1 / CC) * DP + (c1 % CC);
                if (r0 < NN) {
                    if (c0 < COLS) out[(long)r0 * OST + cp0] = acc[mi][ni][0];
                    if (c1 < COLS) out[(long)r0 * OST + cp1] = acc[mi][ni][1];
                }
                if (r1 < NN) {
                    if (c0 < COLS) out[(long)r1 * OST + cp0] = acc[mi][ni][2];
                    if (c1 < COLS) out[(long)r1 * OST + cp1] = acc[mi][ni][3];
                }
            }
        }
    }
    if (PADMAP) {
        for (int idx = tid; idx < BR * HH; idx += TPB) {
            int r = idx >> 2, h = idx & 3;
            if (n0 + r < NN) out[(long)(n0 + r) * OST + h * DP + (DP - 1)] = 0.f;
        }
    }

    if (ELR) {
        float pel[4] = {0.f, 0.f, 0.f, 0.f};
        float per_[4] = {0.f, 0.f, 0.f, 0.f};
#pragma unroll
        for (int ni = 0; ni < 4; ni++) {
            int c0 = ncol + ni * 8 + 2 * q;
            float a0 = al[c0], a1 = al[c0 + 1];
            float b0 = ar[c0], b1 = ar[c0 + 1];
            pel[0] += acc[0][ni][0] * a0 + acc[0][ni][1] * a1;
            pel[1] += acc[0][ni][2] * a0 + acc[0][ni][3] * a1;
            pel[2] += acc[1][ni][0] * a0 + acc[1][ni][1] * a1;
            pel[3] += acc[1][ni][2] * a0 + acc[1][ni][3] * a1;
            per_[0] += acc[0][ni][0] * b0 + acc[0][ni][1] * b1;
            per_[1] += acc[0][ni][2] * b0 + acc[0][ni][3] * b1;
            per_[2] += acc[1][ni][0] * b0 + acc[1][ni][1] * b1;
            per_[3] += acc[1][ni][2] * b0 + acc[1][ni][3] * b1;
        }
#pragma unroll
        for (int o = 1; o < 4; o <<= 1) {
#pragma unroll
            for (int j = 0; j < 4; j++) {
                pel[j]  += __shfl_xor_sync(0xffffffffu, pel[j],  o);
                per_[j] += __shfl_xor_sync(0xffffffffu, per_[j], o);
            }
        }
        int h = ncol >> 5;
        float bm = -CUDART_INF_F;
        if (q == 0) {
            int lr[4] = {mrow + g, mrow + g + 8, mrow + 16 + g, mrow + 24 + g};
#pragma unroll
            for (int j = 0; j < 4; j++) {
                int n = n0 + lr[j];
                if (n < NN) {
                    g_el[n * HH + h] = pel[j];
                    g_er[n * HH + h] = per_[j];
                    bm = fmaxf(bm, pel[j]);
                }
            }
        }
#pragma unroll
        for (int o = 16; o; o >>= 1) bm = fmaxf(bm, __shfl_xor_sync(0xffffffffu, bm, o));
        if (lane == 0) atomicMax(&mslot[h], enc_f(bm));
    }
}

// elr layer 2: warp per (n,h); block-max + atomicMax.
__global__ void elr2_k(const float* __restrict__ fs, const float* __restrict__ al,
                       const float* __restrict__ ar, unsigned* __restrict__ mslot) {
    __shared__ float s_el[8];
    int wib = threadIdx.x >> 5;
    int lane = threadIdx.x & 31;
    int w = blockIdx.x * 8 + wib;
    bool valid = (w < NN * HH);
    int n = w >> 2, h = w & 3;
    float sl = 0.f, sr = 0.f;
    if (valid) {
        for (int d = lane; d < CC; d += 32) {
            float v = fs[(long)n * HCP + h * DP + d];
            sl += v * al[h * CC + d];
            sr += v * ar[h * CC + d];
        }
    }
#pragma unroll
    for (int o = 16; o; o >>= 1) {
        sl += __shfl_xor_sync(0xffffffffu, sl, o);
        sr += __shfl_xor_sync(0xffffffffu, sr, o);
    }
    if (lane == 0) {
        if (valid) { g_el[n * HH + h] = sl; g_er[n * HH + h] = sr; }
        s_el[wib] = valid ? sl : -CUDART_INF_F;
    }
    __syncthreads();
    if (threadIdx.x < 4) {
        float m = fmaxf(s_el[threadIdx.x], s_el[threadIdx.x + 4]);
        atomicMax(&mslot[threadIdx.x], enc_f(m));
    }
}

// ---------------------------------------------------------------------------
// Gather layers 0/1: warp per node, 4 heads.
// ---------------------------------------------------------------------------
template<bool RELU>
__global__ void gather_node_k(const float* __restrict__ fs, float* __restrict__ out,
                              const unsigned* __restrict__ mslot) {
    __shared__ float4 sm_ex[8][32];
    int wib = threadIdx.x >> 5;
    int w = blockIdx.x * 8 + wib;
    int lane = threadIdx.x & 31;
    if (w >= NN) return;
    int n = w;
    int myh = lane >> 3;
    int beg = g_row_ptr[n], end = g_row_ptr[n + 1];
    float4 er4 = ((const float4*)g_er)[n];
    uint4 mu = *(const uint4*)mslot;
    float4 m4 = lrelu4(make_float4(dec_f(mu.x) + er4.x, dec_f(mu.y) + er4.y,
                                   dec_f(mu.z) + er4.z, dec_f(mu.w) + er4.w));

    const float4* fs4 = (const float4*)fs;
    float4 acc = make_float4(0.f, 0.f, 0.f, 0.f);
    float4 ssum = make_float4(0.f, 0.f, 0.f, 0.f);

    for (int i0 = beg; i0 < end; i0 += 32) {
        int i = i0 + lane;
        int s = 0;
        float4 ex = make_float4(0.f, 0.f, 0.f, 0.f);
        if (i < end) {
            s = g_col_src[i];
            float4 el4 = ((const float4*)g_el)[s];
            float4 e4 = lrelu4(make_float4(el4.x + er4.x, el4.y + er4.y,
                                           el4.z + er4.z, el4.w + er4.w));
            ex = make_float4(__expf(e4.x - m4.x), __expf(e4.y - m4.y),
                             __expf(e4.z - m4.z), __expf(e4.w - m4.w));
            ssum.x += ex.x; ssum.y += ex.y; ssum.z += ex.z; ssum.w += ex.w;
        }
        sm_ex[wib][lane] = ex;
        __syncwarp();
        int cnt = min(32, end - i0);
        const float* exbase = (const float*)&sm_ex[wib][0] + myh;
        if (cnt == 32) {
#pragma unroll
            for (int j = 0; j < 32; j++) {
                int sj = __shfl_sync(0xffffffffu, s, j);
                float exj = exbase[j * 4];
                float4 r = fs4[(long)sj * 32 + lane];
                acc.x += exj * r.x; acc.y += exj * r.y;
                acc.z += exj * r.z; acc.w += exj * r.w;
            }
        } else {
            for (int j = 0; j < cnt; j++) {
                int sj = __shfl_sync(0xffffffffu, s, j);
                float exj = exbase[j * 4];
                float4 r = fs4[(long)sj * 32 + lane];
                acc.x += exj * r.x; acc.y += exj * r.y;
                acc.z += exj * r.z; acc.w += exj * r.w;
            }
        }
        __syncwarp();
    }
#pragma unroll
    for (int o = 16; o; o >>= 1) {
        ssum.x += __shfl_xor_sync(0xffffffffu, ssum.x, o);
        ssum.y += __shfl_xor_sync(0xffffffffu, ssum.y, o);
        ssum.z += __shfl_xor_sync(0xffffffffu, ssum.z, o);
        ssum.w += __shfl_xor_sync(0xffffffffu, ssum.w, o);
    }
    float s_my = (myh == 0) ? ssum.x : (myh == 1) ? ssum.y : (myh == 2) ? ssum.z : ssum.w;
    float inv = (s_my > 0.f) ? 1.f / s_my : 0.f;
    float4 o4 = make_float4(acc.x * inv, acc.y * inv, acc.z * inv, acc.w * inv);
    if (RELU) {
        o4.x = fmaxf(o4.x, 0.f); o4.y = fmaxf(o4.y, 0.f);
        o4.z = fmaxf(o4.z, 0.f); o4.w = fmaxf(o4.w, 0.f);
    }
    ((float4*)out)[(long)n * 32 + lane] = o4;
}

// ---------------------------------------------------------------------------
// Gather layer 2 + fused head-mean + log_softmax.
// ---------------------------------------------------------------------------
__global__ void gather2_final_k(const float* __restrict__ fs, float* __restrict__ out,
                                const unsigned* __restrict__ mslot) {
    __shared__ float4 sm_ex[8][32];
    __shared__ float  sm_row[8][HCP];
    int wib = threadIdx.x >> 5;
    int w = blockIdx.x * 8 + wib;
    int lane = threadIdx.x & 31;
    if (w >= NN) return;
    int n = w;
    int ha = lane / 12;
    int hb = (lane + 32) / 12;
    bool hasb = (lane < 16);
    int beg = g_row_ptr[n], end = g_row_ptr[n + 1];
    float4 er4 = ((const float4*)g_er)[n];
    uint4 mu = *(const uint4*)mslot;
    float4 m4 = lrelu4(make_float4(dec_f(mu.x) + er4.x, dec_f(mu.y) + er4.y,
                                   dec_f(mu.z) + er4.z, dec_f(mu.w) + er4.w));

    const float4* fs4 = (const float4*)fs;
    float4 acca = make_float4(0.f, 0.f, 0.f, 0.f);
    float4 accb = make_float4(0.f, 0.f, 0.f, 0.f);
    float4 ssum = make_float4(0.f, 0.f, 0.f, 0.f);

    for (int i0 = beg; i0 < end; i0 += 32) {
        int i = i0 + lane;
        int s = 0;
        float4 ex = make_float4(0.f, 0.f, 0.f, 0.f);
        if (i < end) {
            s = g_col_src[i];
            float4 el4 = ((const float4*)g_el)[s];
            float4 e4 = lrelu4(make_float4(el4.x + er4.x, el4.y + er4.y,
                                           el4.z + er4.z, el4.w + er4.w));
            ex = make_float4(__expf(e4.x - m4.x), __expf(e4.y - m4.y),
                             __expf(e4.z - m4.z), __expf(e4.w - m4.w));
            ssum.x += ex.x; ssum.y += ex.y; ssum.z += ex.z; ssum.w += ex.w;
        }
        sm_ex[wib][lane] = ex;
        __syncwarp();
        int cnt = min(32, end - i0);
        const float* exb = (const float*)&sm_ex[wib][0];
        for (int j = 0; j < cnt; j++) {
            int sj = __shfl_sync(0xffffffffu, s, j);
            float exja = exb[j * 4 + ha];
            long rb = (long)sj * 48;
            float4 r = fs4[rb + lane];
            acca.x += exja * r.x; acca.y += exja * r.y;
            acca.z += exja * r.z; acca.w += exja * r.w;
            if (hasb) {
                float exjb = exb[j * 4 + hb];
                float4 r2 = fs4[rb + 32 + lane];
                accb.x += exjb * r2.x; accb.y += exjb * r2.y;
                accb.z += exjb * r2.z; accb.w += exjb * r2.w;
            }
        }
        __syncwarp();
    }
#pragma unroll
    for (int o = 16; o; o >>= 1) {
        ssum.x += __shfl_xor_sync(0xffffffffu, ssum.x, o);
        ssum.y += __shfl_xor_sync(0xffffffffu, ssum.y, o);
        ssum.z += __shfl_xor_sync(0xffffffffu, ssum.z, o);
        ssum.w += __shfl_xor_sync(0xffffffffu, ssum.w, o);
    }
    float sa = (ha == 0) ? ssum.x : (ha == 1) ? ssum.y : (ha == 2) ? ssum.z : ssum.w;
    float inva = (sa > 0.f) ? 1.f / sa : 0.f;
    ((float4*)&sm_row[wib][0])[lane] =
        make_float4(acca.x * inva, acca.y * inva, acca.z * inva, acca.w * inva);
    if (hasb) {
        float sb = (hb == 0) ? ssum.x : (hb == 1) ? ssum.y : (hb == 2) ? ssum.z : ssum.w;
        float invb = (sb > 0.f) ? 1.f / sb : 0.f;
        ((float4*)&sm_row[wib][0])[32 + lane] =
            make_float4(accb.x * invb, accb.y * invb, accb.z * invb, accb.w * invb);
    }
    __syncwarp();

    const float* row = &sm_row[wib][0];
    float v0 = 0.f, v1 = 0.f;
    int c0 = lane, c1 = lane + 32;
    if (c0 < CC) {
#pragma unroll
        for (int h = 0; h < HH; h++) v0 += row[h * DP + c0];
        v0 *= 0.25f;
    }
    if (c1 < CC) {
#pragma unroll
        for (int h = 0; h < HH; h++) v1 += row[h * DP + c1];
        v1 *= 0.25f;
    }
    float a = (c0 < CC) ? v0 : -CUDART_INF_F;
    float b = (c1 < CC) ? v1 : -CUDART_INF_F;
    float m = fmaxf(a, b);
#pragma unroll
    for (int o = 16; o; o >>= 1) m = fmaxf(m, __shfl_xor_sync(0xffffffffu, m, o));
    float s = 0.f;
    if (c0 < CC) s += __expf(v0 - m);
    if (c1 < CC) s += __expf(v1 - m);
#pragma unroll
    for (int o = 16; o; o >>= 1) s += __shfl_xor_sync(0xffffffffu, s, o);
    float lse = m + logf(s);
    if (c0 < CC) out[(long)n * CC + c0] = v0 - lse;
    if (c1 < CC) out[(long)n * CC + c1] = v1 - lse;
}

// ---------------------------------------------------------------------------
extern "C" void kernel_launch(void* const* d_in, const int* in_sizes, int n_in,
                              void* d_out, int out_size) {
    const float* x   = (const float*)d_in[0];
    const float* W0  = (const float*)d_in[1];
    const float* al0 = (const float*)d_in[2];
    const float* ar0 = (const float*)d_in[3];
    const float* W1  = (const float*)d_in[4];
    const float* al1 = (const float*)d_in[5];
    const float* ar1 = (const float*)d_in[6];
    const float* W2  = (const float*)d_in[7];
    const float* al2 = (const float*)d_in[8];
    const float* ar2 = (const float*)d_in[9];
    const int*   src = (const int*)d_in[10];
    const int*   dst = (const int*)d_in[11];
    float* out = (float*)d_out;

    float* fs = nullptr; float* hbuf = nullptr; unsigned* mx = nullptr;
    cudaGetSymbolAddress((void**)&fs,  g_fs);
    cudaGetSymbolAddress((void**)&hbuf, g_h);
    cudaGetSymbolAddress((void**)&mx,  g_maxel_enc);

    auto g0 = gemm_mma_k<FIN, 112, FIN, 64, 128, 128, 2, 256, HD,  false, true>;
    auto g1 = gemm_mma_k<HD,  128, HD,  64, 128, 128, 2, 256, HD,  false, true>;
    auto g2 = gemm_mma_k<HD,  128, HD,  32, 192, 188, 1, 192, HCP, true,  false>;
    const int smem0 = (64 + 128) * (112 + 8) * 2;
    const int smem1 = (64 + 128) * (128 + 8) * 2;
    const int smem2 = (32 + 192) * (128 + 8) * 2;

    static cudaStream_t s_csr = nullptr;
    static cudaEvent_t  ev_fork = nullptr, ev_join = nullptr;
    if (s_csr == nullptr) {
        cudaStreamCreateWithFlags(&s_csr, cudaStreamNonBlocking);
        cudaEventCreateWithFlags(&ev_fork, cudaEventDisableTiming);
        cudaEventCreateWithFlags(&ev_join, cudaEventDisableTiming);
        cudaFuncSetAttribute(g0, cudaFuncAttributeMaxDynamicSharedMemorySize, smem0);
        cudaFuncSetAttribute(g1, cudaFuncAttributeMaxDynamicSharedMemorySize, smem1);
        cudaFuncSetAttribute(g2, cudaFuncAttributeMaxDynamicSharedMemorySize, smem2);
    }

    const int node_blocks = (NN + 7) / 8;
    const int nh_blocks   = (NN * HH + 7) / 8;
    const int gblocks64   = (NN + 63) / 64;
    const int gblocks32   = (NN + 31) / 32;

    init_k<<<1, 32>>>();

    // ---- fork: CSR build on side stream ----
    cudaEventRecord(ev_fork, 0);
    cudaStreamWaitEvent(s_csr, ev_fork, 0);
    zero_counts_k<<<(NN + 255) / 256, 256, 0, s_csr>>>();
    count_k<<<(EE + 255) / 256, 256, 0, s_csr>>>(dst);
    scanA_k<<<SCAN_NB, 1024, 0, s_csr>>>();
    scanB_k<<<1, 32, 0, s_csr>>>();
    scanC_k<<<SCAN_NB, 1024, 0, s_csr>>>();
    fill_k<<<(EE + 255) / 256, 256, 0, s_csr>>>(src, dst);
    cudaEventRecord(ev_join, s_csr);

    // ---- layer 0 (elr fused into gemm epilogue) ----
    g0<<<gblocks64, 256, smem0>>>(x, W0, fs, mx + 0, al0, ar0);
    cudaStreamWaitEvent(0, ev_join, 0);
    gather_node_k<true><<<node_blocks, 256>>>(fs, hbuf, mx + 0);

    // ---- layer 1 ----
    g1<<<gblocks64, 256, smem1>>>(hbuf, W1, fs, mx + 4, al1, ar1);
    gather_node_k<true><<<node_blocks, 256>>>(fs, hbuf, mx + 4);

    // ---- layer 2 (padded 4x48) + fused finale ----
    g2<<<gblocks32, 192, smem2>>>(hbuf, W2, fs, mx + 8, nullptr, nullptr);
    elr2_k<<<nh_blocks, 256>>>(fs, al2, ar2, mx + 8);
    gather2_final_k<<<node_blocks, 256>>>(fs, out, mx + 8);
}

// round 15
// speedup vs baseline: 1.4430x; 1.4430x over previous
#include <cuda_runtime.h>
#include <cuda_bf16.h>
#include <cuda_fp16.h>
#include <math_constants.h>

// ---------------------------------------------------------------------------
// GAT_50861002719235: 3-layer GAT, N=50000, E=1.6M, H=4, D=32/32/47
// R14 re-bench (unchanged): R13 + multi-block CSR scan.
// Component metrics said -57us; total said +129us; resolving the anomaly.
// ---------------------------------------------------------------------------

#define NN 50000
#define EE 1600000
#define HH 4
#define FIN 100
#define HD 128
#define CC 47
#define DP 48
#define HCP 192
#define NEG_SLOPE 0.2f

#define SCAN_B 2048
#define SCAN_NB ((NN + SCAN_B - 1) / SCAN_B)   // 25

__device__ int      g_row_ptr[NN + 1];
__device__ int      g_cursor[NN];
__device__ int      g_col_src[EE];
__device__ int      g_bsum[SCAN_NB];
__device__ int      g_boff[SCAN_NB];
__device__ float    g_fs[NN * HCP];
__device__ float    g_h [NN * HCP];
__device__ float    g_el[NN * HH];
__device__ float    g_er[NN * HH];
__device__ unsigned g_maxel_enc[12];

__device__ __forceinline__ float lrelu(float x) { return (x >= 0.f) ? x : NEG_SLOPE * x; }
__device__ __forceinline__ float4 lrelu4(float4 v) {
    return make_float4(lrelu(v.x), lrelu(v.y), lrelu(v.z), lrelu(v.w));
}
__device__ __forceinline__ unsigned enc_f(float f) {
    unsigned b = __float_as_uint(f);
    return (b & 0x80000000u) ? ~b : (b | 0x80000000u);
}
__device__ __forceinline__ float dec_f(unsigned u) {
    unsigned b = (u & 0x80000000u) ? (u ^ 0x80000000u) : ~u;
    return __uint_as_float(b);
}

__global__ void init_k() {
    if (threadIdx.x < 12) g_maxel_enc[threadIdx.x] = 0u;
}

// ---------------------------------------------------------------------------
// CSR build (multi-block scan)
// ---------------------------------------------------------------------------
__global__ void zero_counts_k() {
    int i = blockIdx.x * blockDim.x + threadIdx.x;
    if (i < NN) g_cursor[i] = 0;
}
__global__ void count_k(const int* __restrict__ dst) {
    int e = blockIdx.x * blockDim.x + threadIdx.x;
    if (e < EE) atomicAdd(&g_cursor[dst[e]], 1);
}
__global__ void scanA_k() {
    __shared__ int sh[1024];
    int b = blockIdx.x, t = threadIdx.x;
    int i0 = b * SCAN_B + t * 2;
    int c0 = (i0     < NN) ? g_cursor[i0]     : 0;
    int c1 = (i0 + 1 < NN) ? g_cursor[i0 + 1] : 0;
    sh[t] = c0 + c1;
    __syncthreads();
    for (int o = 512; o >= 1; o >>= 1) {
        if (t < o) sh[t] += sh[t + o];
        __syncthreads();
    }
    if (t == 0) g_bsum[b] = sh[0];
}
__global__ void scanB_k() {
    int t = threadIdx.x;
    int s = (t < SCAN_NB) ? g_bsum[t] : 0;
    int v = s;
    for (int o = 1; o < 32; o <<= 1) {
        int u = __shfl_up_sync(0xffffffffu, v, o);
        if (t >= o) v += u;
    }
    if (t < SCAN_NB) g_boff[t] = v - s;
    if (t == 31) g_row_ptr[NN] = v;
}
__global__ void scanC_k() {
    __shared__ int sh[1024];
    int b = blockIdx.x, t = threadIdx.x;
    int i0 = b * SCAN_B + t * 2;
    int c0 = (i0     < NN) ? g_cursor[i0]     : 0;
    int c1 = (i0 + 1 < NN) ? g_cursor[i0 + 1] : 0;
    int pair = c0 + c1;
    sh[t] = pair;
    __syncthreads();
    for (int o = 1; o < 1024; o <<= 1) {
        int u = (t >= o) ? sh[t - o] : 0;
        __syncthreads();
        sh[t] += u;
        __syncthreads();
    }
    int base = g_boff[b] + sh[t] - pair;
    if (i0 < NN)     { g_row_ptr[i0]     = base;      g_cursor[i0]     = base; }
    if (i0 + 1 < NN) { g_row_ptr[i0 + 1] = base + c0; g_cursor[i0 + 1] = base + c0; }
}
__global__ void fill_k(const int* __restrict__ src, const int* __restrict__ dst) {
    int e = blockIdx.x * blockDim.x + threadIdx.x;
    if (e < EE) { int p = atomicAdd(&g_cursor[dst[e]], 1); g_col_src[p] = src[e]; }
}

// ---------------------------------------------------------------------------
// Tensor-core GEMM with optional fused el/er epilogue (layers 0/1).
// ---------------------------------------------------------------------------
__device__ __forceinline__ void mma16816(float* c, const unsigned* a,
                                         unsigned b0, unsigned b1) {
    asm volatile(
        "mma.sync.aligned.m16n8k16.row.col.f32.f16.f16.f32 "
        "{%0,%1,%2,%3}, {%4,%5,%6,%7}, {%8,%9}, {%0,%1,%2,%3};"
        : "+f"(c[0]), "+f"(c[1]), "+f"(c[2]), "+f"(c[3])
        : "r"(a[0]), "r"(a[1]), "r"(a[2]), "r"(a[3]), "r"(b0), "r"(b1));
}

template<int K, int KP, int AST, int BR, int BCP, int COLS, int NWR, int TPB,
         int OST, bool PADMAP, bool ELR>
__global__ void gemm_mma_k(const float* __restrict__ A, const float* __restrict__ W,
                           float* __restrict__ out, unsigned* __restrict__ mslot,
                           const float* __restrict__ al, const float* __restrict__ ar) {
    extern __shared__ __half smem[];
    const int STR = KP + 8;
    __half* A_s = smem;
    __half* W_s = smem + BR * STR;
    int n0 = blockIdx.x * BR;
    int tid = threadIdx.x;

    for (int idx = tid; idx < BR * (KP / 2); idx += TPB) {
        int r = idx / (KP / 2);
        int k = (idx % (KP / 2)) * 2;
        int n = n0 + r;
        __half2 hv;
        if (n < NN && k + 1 < K) {
            float2 f = *(const float2*)(A + (long)n * AST + k);
            hv = __float22half2_rn(f);
        } else {
            hv = __half2half2(__float2half_rn(0.f));
        }
        *(__half2*)&A_s[r * STR + k] = hv;
    }
    for (int idx = tid; idx < BCP * KP; idx += TPB) {
        int k = idx / BCP;
        int c = idx % BCP;
        float v = (c < COLS && k < K) ? W[(long)k * COLS + c] : 0.f;
        W_s[c * STR + k] = __float2half_rn(v);
    }
    __syncthreads();

    int wid = tid >> 5, lane = tid & 31;
    int g = lane >> 2, q = lane & 3;
    int mrow = (wid % NWR) * 32;
    int ncol = (wid / NWR) * 32;

    float acc[2][4][4];
#pragma unroll
    for (int mi = 0; mi < 2; mi++)
#pragma unroll
        for (int ni = 0; ni < 4; ni++)
#pragma unroll
            for (int p = 0; p < 4; p++) acc[mi][ni][p] = 0.f;

#pragma unroll
    for (int ks = 0; ks < KP / 16; ks++) {
        int k0 = ks * 16;
        unsigned a[2][4];
#pragma unroll
        for (int mi = 0; mi < 2; mi++) {
            int rb = mrow + mi * 16;
            a[mi][0] = *(const unsigned*)&A_s[(rb + g) * STR + k0 + 2 * q];
            a[mi][1] = *(const unsigned*)&A_s[(rb + g + 8) * STR + k0 + 2 * q];
            a[mi][2] = *(const unsigned*)&A_s[(rb + g) * STR + k0 + 2 * q + 8];
            a[mi][3] = *(const unsigned*)&A_s[(rb + g + 8) * STR + k0 + 2 * q + 8];
        }
#pragma unroll
        for (int ni = 0; ni < 4; ni++) {
            int cb = ncol + ni * 8 + g;
            unsigned b0 = *(const unsigned*)&W_s[cb * STR + k0 + 2 * q];
            unsigned b1 = *(const unsigned*)&W_s[cb * STR + k0 + 2 * q + 8];
            mma16816(acc[0][ni], a[0], b0, b1);
            mma16816(acc[1][ni], a[1], b0, b1);
        }
    }

#pragma unroll
    for (int mi = 0; mi < 2; mi++) {
#pragma unroll
        for (int ni = 0; ni < 4; ni++) {
            int c0 = ncol + ni * 8 + 2 * q;
            int r0 = n0 + mrow + mi * 16 + g;
            int r1 = r0 + 8;
            if (!PADMAP) {
                if (r0 < NN) *(float2*)&out[(long)r0 * OST + c0] =
                    make_float2(acc[mi][ni][0], acc[mi][ni][1]);
                if (r1 < NN) *(float2*)&out[(long)r1 * OST + c0] =
                    make_float2(acc[mi][ni][2], acc[mi][ni][3]);
            } else {
                int c1 = c0 + 1;
                int cp0 = (c0 / CC) * DP + (c0 % CC);
                int cp1 = (c1 / CC) * DP + (c1 % CC);
                if (r0 < NN) {
                    if (c0 < COLS) out[(long)r0 * OST + cp0] = acc[mi][ni][0];
                    if (c1 < COLS) out[(long)r0 * OST + cp1] = acc[mi][ni][1];
                }
                if (r1 < NN) {
                    if (c0 < COLS) out[(long)r1 * OST + cp0] = acc[mi][ni][2];
                    if (c1 < COLS) out[(long)r1 * OST + cp1] = acc[mi][ni][3];
                }
            }
        }
    }
    if (PADMAP) {
        for (int idx = tid; idx < BR * HH; idx += TPB) {
            int r = idx >> 2, h = idx & 3;
            if (n0 + r < NN) out[(long)(n0 + r) * OST + h * DP + (DP - 1)] = 0.f;
        }
    }

    if (ELR) {
        float pel[4] = {0.f, 0.f, 0.f, 0.f};
        float per_[4] = {0.f, 0.f, 0.f, 0.f};
#pragma unroll
        for (int ni = 0; ni < 4; ni++) {
            int c0 = ncol + ni * 8 + 2 * q;
            float a0 = al[c0], a1 = al[c0 + 1];
            float b0 = ar[c0], b1 = ar[c0 + 1];
            pel[0] += acc[0][ni][0] * a0 + acc[0][ni][1] * a1;
            pel[1] += acc[0][ni][2] * a0 + acc[0][ni][3] * a1;
            pel[2] += acc[1][ni][0] * a0 + acc[1][ni][1] * a1;
            pel[3] += acc[1][ni][2] * a0 + acc[1][ni][3] * a1;
            per_[0] += acc[0][ni][0] * b0 + acc[0][ni][1] * b1;
            per_[1] += acc[0][ni][2] * b0 + acc[0][ni][3] * b1;
            per_[2] += acc[1][ni][0] * b0 + acc[1][ni][1] * b1;
            per_[3] += acc[1][ni][2] * b0 + acc[1][ni][3] * b1;
        }
#pragma unroll
        for (int o = 1; o < 4; o <<= 1) {
#pragma unroll
            for (int j = 0; j < 4; j++) {
                pel[j]  += __shfl_xor_sync(0xffffffffu, pel[j],  o);
                per_[j] += __shfl_xor_sync(0xffffffffu, per_[j], o);
            }
        }
        int h = ncol >> 5;
        float bm = -CUDART_INF_F;
        if (q == 0) {
            int lr[4] = {mrow + g, mrow + g + 8, mrow + 16 + g, mrow + 24 + g};
#pragma unroll
            for (int j = 0; j < 4; j++) {
                int n = n0 + lr[j];
                if (n < NN) {
                    g_el[n * HH + h] = pel[j];
                    g_er[n * HH + h] = per_[j];
                    bm = fmaxf(bm, pel[j]);
                }
            }
        }
#pragma unroll
        for (int o = 16; o; o >>= 1) bm = fmaxf(bm, __shfl_xor_sync(0xffffffffu, bm, o));
        if (lane == 0) atomicMax(&mslot[h], enc_f(bm));
    }
}

// elr layer 2: warp per (n,h); block-max + atomicMax.
__global__ void elr2_k(const float* __restrict__ fs, const float* __restrict__ al,
                       const float* __restrict__ ar, unsigned* __restrict__ mslot) {
    __shared__ float s_el[8];
    int wib = threadIdx.x >> 5;
    int lane = threadIdx.x & 31;
    int w = blockIdx.x * 8 + wib;
    bool valid = (w < NN * HH);
    int n = w >> 2, h = w & 3;
    float sl = 0.f, sr = 0.f;
    if (valid) {
        for (int d = lane; d < CC; d += 32) {
            float v = fs[(long)n * HCP + h * DP + d];
            sl += v * al[h * CC + d];
            sr += v * ar[h * CC + d];
        }
    }
#pragma unroll
    for (int o = 16; o; o >>= 1) {
        sl += __shfl_xor_sync(0xffffffffu, sl, o);
        sr += __shfl_xor_sync(0xffffffffu, sr, o);
    }
    if (lane == 0) {
        if (valid) { g_el[n * HH + h] = sl; g_er[n * HH + h] = sr; }
        s_el[wib] = valid ? sl : -CUDART_INF_F;
    }
    __syncthreads();
    if (threadIdx.x < 4) {
        float m = fmaxf(s_el[threadIdx.x], s_el[threadIdx.x + 4]);
        atomicMax(&mslot[threadIdx.x], enc_f(m));
    }
}

// ---------------------------------------------------------------------------
// Gather layers 0/1: warp per node, 4 heads.
// ---------------------------------------------------------------------------
template<bool RELU>
__global__ void gather_node_k(const float* __restrict__ fs, float* __restrict__ out,
                              const unsigned* __restrict__ mslot) {
    __shared__ float4 sm_ex[8][32];
    int wib = threadIdx.x >> 5;
    int w = blockIdx.x * 8 + wib;
    int lane = threadIdx.x & 31;
    if (w >= NN) return;
    int n = w;
    int myh = lane >> 3;
    int beg = g_row_ptr[n], end = g_row_ptr[n + 1];
    float4 er4 = ((const float4*)g_er)[n];
    uint4 mu = *(const uint4*)mslot;
    float4 m4 = lrelu4(make_float4(dec_f(mu.x) + er4.x, dec_f(mu.y) + er4.y,
                                   dec_f(mu.z) + er4.z, dec_f(mu.w) + er4.w));

    const float4* fs4 = (const float4*)fs;
    float4 acc = make_float4(0.f, 0.f, 0.f, 0.f);
    float4 ssum = make_float4(0.f, 0.f, 0.f, 0.f);

    for (int i0 = beg; i0 < end; i0 += 32) {
        int i = i0 + lane;
        int s = 0;
        float4 ex = make_float4(0.f, 0.f, 0.f, 0.f);
        if (i < end) {
            s = g_col_src[i];
            float4 el4 = ((const float4*)g_el)[s];
            float4 e4 = lrelu4(make_float4(el4.x + er4.x, el4.y + er4.y,
                                           el4.z + er4.z, el4.w + er4.w));
            ex = make_float4(__expf(e4.x - m4.x), __expf(e4.y - m4.y),
                             __expf(e4.z - m4.z), __expf(e4.w - m4.w));
            ssum.x += ex.x; ssum.y += ex.y; ssum.z += ex.z; ssum.w += ex.w;
        }
        sm_ex[wib][lane] = ex;
        __syncwarp();
        int cnt = min(32, end - i0);
        const float* exbase = (const float*)&sm_ex[wib][0] + myh;
        if (cnt == 32) {
#pragma unroll
            for (int j = 0; j < 32; j++) {
                int sj = __shfl_sync(0xffffffffu, s, j);
                float exj = exbase[j * 4];
                float4 r = fs4[(long)sj * 32 + lane];
                acc.x += exj * r.x; acc.y += exj * r.y;
                acc.z += exj * r.z; acc.w += exj * r.w;
            }
        } else {
            for (int j = 0; j < cnt; j++) {
                int sj = __shfl_sync(0xffffffffu, s, j);
                float exj = exbase[j * 4];
                float4 r = fs4[(long)sj * 32 + lane];
                acc.x += exj * r.x; acc.y += exj * r.y;
                acc.z += exj * r.z; acc.w += exj * r.w;
            }
        }
        __syncwarp();
    }
#pragma unroll
    for (int o = 16; o; o >>= 1) {
        ssum.x += __shfl_xor_sync(0xffffffffu, ssum.x, o);
        ssum.y += __shfl_xor_sync(0xffffffffu, ssum.y, o);
        ssum.z += __shfl_xor_sync(0xffffffffu, ssum.z, o);
        ssum.w += __shfl_xor_sync(0xffffffffu, ssum.w, o);
    }
    float s_my = (myh == 0) ? ssum.x : (myh == 1) ? ssum.y : (myh == 2) ? ssum.z : ssum.w;
    float inv = (s_my > 0.f) ? 1.f / s_my : 0.f;
    float4 o4 = make_float4(acc.x * inv, acc.y * inv, acc.z * inv, acc.w * inv);
    if (RELU) {
        o4.x = fmaxf(o4.x, 0.f); o4.y = fmaxf(o4.y, 0.f);
        o4.z = fmaxf(o4.z, 0.f); o4.w = fmaxf(o4.w, 0.f);
    }
    ((float4*)out)[(long)n * 32 + lane] = o4;
}

// ---------------------------------------------------------------------------
// Gather layer 2 + fused head-mean + log_softmax.
// ---------------------------------------------------------------------------
__global__ void gather2_final_k(const float* __restrict__ fs, float* __restrict__ out,
                                const unsigned* __restrict__ mslot) {
    __shared__ float4 sm_ex[8][32];
    __shared__ float  sm_row[8][HCP];
    int wib = threadIdx.x >> 5;
    int w = blockIdx.x * 8 + wib;
    int lane = threadIdx.x & 31;
    if (w >= NN) return;
    int n = w;
    int ha = lane / 12;
    int hb = (lane + 32) / 12;
    bool hasb = (lane < 16);
    int beg = g_row_ptr[n], end = g_row_ptr[n + 1];
    float4 er4 = ((const float4*)g_er)[n];
    uint4 mu = *(const uint4*)mslot;
    float4 m4 = lrelu4(make_float4(dec_f(mu.x) + er4.x, dec_f(mu.y) + er4.y,
                                   dec_f(mu.z) + er4.z, dec_f(mu.w) + er4.w));

    const float4* fs4 = (const float4*)fs;
    float4 acca = make_float4(0.f, 0.f, 0.f, 0.f);
    float4 accb = make_float4(0.f, 0.f, 0.f, 0.f);
    float4 ssum = make_float4(0.f, 0.f, 0.f, 0.f);

    for (int i0 = beg; i0 < end; i0 += 32) {
        int i = i0 + lane;
        int s = 0;
        float4 ex = make_float4(0.f, 0.f, 0.f, 0.f);
        if (i < end) {
            s = g_col_src[i];
            float4 el4 = ((const float4*)g_el)[s];
            float4 e4 = lrelu4(make_float4(el4.x + er4.x, el4.y + er4.y,
                                           el4.z + er4.z, el4.w + er4.w));
            ex = make_float4(__expf(e4.x - m4.x), __expf(e4.y - m4.y),
                             __expf(e4.z - m4.z), __expf(e4.w - m4.w));
            ssum.x += ex.x; ssum.y += ex.y; ssum.z += ex.z; ssum.w += ex.w;
        }
        sm_ex[wib][lane] = ex;
        __syncwarp();
        int cnt = min(32, end - i0);
        const float* exb = (const float*)&sm_ex[wib][0];
        for (int j = 0; j < cnt; j++) {
            int sj = __shfl_sync(0xffffffffu, s, j);
            float exja = exb[j * 4 + ha];
            long rb = (long)sj * 48;
            float4 r = fs4[rb + lane];
            acca.x += exja * r.x; acca.y += exja * r.y;
            acca.z += exja * r.z; acca.w += exja * r.w;
            if (hasb) {
                float exjb = exb[j * 4 + hb];
                float4 r2 = fs4[rb + 32 + lane];
                accb.x += exjb * r2.x; accb.y += exjb * r2.y;
                accb.z += exjb * r2.z; accb.w += exjb * r2.w;
            }
        }
        __syncwarp();
    }
#pragma unroll
    for (int o = 16; o; o >>= 1) {
        ssum.x += __shfl_xor_sync(0xffffffffu, ssum.x, o);
        ssum.y += __shfl_xor_sync(0xffffffffu, ssum.y, o);
        ssum.z += __shfl_xor_sync(0xffffffffu, ssum.z, o);
        ssum.w += __shfl_xor_sync(0xffffffffu, ssum.w, o);
    }
    float sa = (ha == 0) ? ssum.x : (ha == 1) ? ssum.y : (ha == 2) ? ssum.z : ssum.w;
    float inva = (sa > 0.f) ? 1.f / sa : 0.f;
    ((float4*)&sm_row[wib][0])[lane] =
        make_float4(acca.x * inva, acca.y * inva, acca.z * inva, acca.w * inva);
    if (hasb) {
        float sb = (hb == 0) ? ssum.x : (hb == 1) ? ssum.y : (hb == 2) ? ssum.z : ssum.w;
        float invb = (sb > 0.f) ? 1.f / sb : 0.f;
        ((float4*)&sm_row[wib][0])[32 + lane] =
            make_float4(accb.x * invb, accb.y * invb, accb.z * invb, accb.w * invb);
    }
    __syncwarp();

    const float* row = &sm_row[wib][0];
    float v0 = 0.f, v1 = 0.f;
    int c0 = lane, c1 = lane + 32;
    if (c0 < CC) {
#pragma unroll
        for (int h = 0; h < HH; h++) v0 += row[h * DP + c0];
        v0 *= 0.25f;
    }
    if (c1 < CC) {
#pragma unroll
        for (int h = 0; h < HH; h++) v1 += row[h * DP + c1];
        v1 *= 0.25f;
    }
    float a = (c0 < CC) ? v0 : -CUDART_INF_F;
    float b = (c1 < CC) ? v1 : -CUDART_INF_F;
    float m = fmaxf(a, b);
#pragma unroll
    for (int o = 16; o; o >>= 1) m = fmaxf(m, __shfl_xor_sync(0xffffffffu, m, o));
    float s = 0.f;
    if (c0 < CC) s += __expf(v0 - m);
    if (c1 < CC) s += __expf(v1 - m);
#pragma unroll
    for (int o = 16; o; o >>= 1) s += __shfl_xor_sync(0xffffffffu, s, o);
    float lse = m + logf(s);
    if (c0 < CC) out[(long)n * CC + c0] = v0 - lse;
    if (c1 < CC) out[(long)n * CC + c1] = v1 - lse;
}

// ---------------------------------------------------------------------------
extern "C" void kernel_launch(void* const* d_in, const int* in_sizes, int n_in,
                              void* d_out, int out_size) {
    const float* x   = (const float*)d_in[0];
    const float* W0  = (const float*)d_in[1];
    const float* al0 = (const float*)d_in[2];
    const float* ar0 = (const float*)d_in[3];
    const float* W1  = (const float*)d_in[4];
    const float* al1 = (const float*)d_in[5];
    const float* ar1 = (const float*)d_in[6];
    const float* W2  = (const float*)d_in[7];
    const float* al2 = (const float*)d_in[8];
    const float* ar2 = (const float*)d_in[9];
    const int*   src = (const int*)d_in[10];
    const int*   dst = (const int*)d_in[11];
    float* out = (float*)d_out;

    float* fs = nullptr; float* hbuf = nullptr; unsigned* mx = nullptr;
    cudaGetSymbolAddress((void**)&fs,  g_fs);
    cudaGetSymbolAddress((void**)&hbuf, g_h);
    cudaGetSymbolAddress((void**)&mx,  g_maxel_enc);

    auto g0 = gemm_mma_k<FIN, 112, FIN, 64, 128, 128, 2, 256, HD,  false, true>;
    auto g1 = gemm_mma_k<HD,  128, HD,  64, 128, 128, 2, 256, HD,  false, true>;
    auto g2 = gemm_mma_k<HD,  128, HD,  32, 192, 188, 1, 192, HCP, true,  false>;
    const int smem0 = (64 + 128) * (112 + 8) * 2;
    const int smem1 = (64 + 128) * (128 + 8) * 2;
    const int smem2 = (32 + 192) * (128 + 8) * 2;

    static cudaStream_t s_csr = nullptr;
    static cudaEvent_t  ev_fork = nullptr, ev_join = nullptr;
    if (s_csr == nullptr) {
        cudaStreamCreateWithFlags(&s_csr, cudaStreamNonBlocking);
        cudaEventCreateWithFlags(&ev_fork, cudaEventDisableTiming);
        cudaEventCreateWithFlags(&ev_join, cudaEventDisableTiming);
        cudaFuncSetAttribute(g0, cudaFuncAttributeMaxDynamicSharedMemorySize, smem0);
        cudaFuncSetAttribute(g1, cudaFuncAttributeMaxDynamicSharedMemorySize, smem1);
        cudaFuncSetAttribute(g2, cudaFuncAttributeMaxDynamicSharedMemorySize, smem2);
    }

    const int node_blocks = (NN + 7) / 8;
    const int nh_blocks   = (NN * HH + 7) / 8;
    const int gblocks64   = (NN + 63) / 64;
    const int gblocks32   = (NN + 31) / 32;

    init_k<<<1, 32>>>();

    // ---- fork: CSR build on side stream ----
    cudaEventRecord(ev_fork, 0);
    cudaStreamWaitEvent(s_csr, ev_fork, 0);
    zero_counts_k<<<(NN + 255) / 256, 256, 0, s_csr>>>();
    count_k<<<(EE + 255) / 256, 256, 0, s_csr>>>(dst);
    scanA_k<<<SCAN_NB, 1024, 0, s_csr>>>();
    scanB_k<<<1, 32, 0, s_csr>>>();
    scanC_k<<<SCAN_NB, 1024, 0, s_csr>>>();
    fill_k<<<(EE + 255) / 256, 256, 0, s_csr>>>(src, dst);
    cudaEventRecord(ev_join, s_csr);

    // ---- layer 0 (elr fused into gemm epilogue) ----
    g0<<<gblocks64, 256, smem0>>>(x, W0, fs, mx + 0, al0, ar0);
    cudaStreamWaitEvent(0, ev_join, 0);
    gather_node_k<true><<<node_blocks, 256>>>(fs, hbuf, mx + 0);

    // ---- layer 1 ----
    g1<<<gblocks64, 256, smem1>>>(hbuf, W1, fs, mx + 4, al1, ar1);
    gather_node_k<true><<<node_blocks, 256>>>(fs, hbuf, mx + 4);

    // ---- layer 2 (padded 4x48) + fused finale ----
    g2<<<gblocks32, 192, smem2>>>(hbuf, W2, fs, mx + 8, nullptr, nullptr);
    elr2_k<<<nh_blocks, 256>>>(fs, al2, ar2, mx + 8);
    gather2_final_k<<<node_blocks, 256>>>(fs, out, mx + 8);
}